// round 11
// baseline (speedup 1.0000x reference)
#include <cuda_runtime.h>
#include <math.h>

#define Bv 8
#define Lv 2048
#define Dv 64
#define BM 32            // query rows per CTA
#define BK 128           // k-tile
#define NTILE (Lv/BK)    // 16
#define NT 256           // 8 warps
#define SCALE 0.125f     // 1/sqrt(64)
#define CTS 65           // C-tile row stride (floats): conflict-free
#define STTS 36          // St_t row stride: 9 float4-units (odd) -> conflict-free
#define QPSU 18          // Qp row stride in ull

// smem floats: Ct 128*65=8320 + St_t 128*36=4608 + Qp 64*18*2=2304 + sums 128 + rinvs 32
#define SMEM_FLOATS (BK*CTS + BK*STTS + Dv*QPSU*2 + BM*4 + BM)   // 15392 fl = 61,568 B

typedef unsigned long long ull;

#define FMA2(d_, a_, b_, c_) \
    asm("fma.rn.f32x2 %0, %1, %2, %3;" : "=l"(d_) : "l"(a_), "l"(b_), "l"(c_))
#define PACKF2(d_, x_, y_) \
    asm("mov.b64 %0, {%1, %2};" : "=l"(d_) : "f"(x_), "f"(y_))
#define UNPACKF2(x_, y_, s_) \
    asm("mov.b64 {%0, %1}, %2;" : "=f"(x_), "=f"(y_) : "l"(s_))
#define CP_ASYNC4(dst_, src_) \
    asm volatile("cp.async.ca.shared.global [%0], [%1], 4;" :: "r"(dst_), "l"(src_))
#define CP_COMMIT() asm volatile("cp.async.commit_group;")
#define CP_WAIT0()  asm volatile("cp.async.wait_group 0;" ::: "memory")

__global__ __launch_bounds__(NT, 3)
void attn_fused_kernel(const float* __restrict__ Q,
                       const float* __restrict__ C,
                       const unsigned char* __restrict__ M,
                       float* __restrict__ out,
                       float* __restrict__ att)
{
    extern __shared__ float smf[];
    float* Ct    = smf;                       // [BK][CTS]   Ct[k][d] at k*65+d
    float* St_t  = Ct + BK*CTS;               // [BK][STTS]  St_t[k][row 0..31]
    ull*   Qp    = (ull*)(St_t + BK*STTS);    // [Dv][QPSU]  row-pair packed Q (pre-scaled)
    float* sums  = (float*)(Qp + Dv*QPSU);    // [BM][4]
    float* rinvs = sums + BM*4;               // [BM]

    const unsigned int ctb =
        (unsigned int)__cvta_generic_to_shared(Ct);   // smem u32 base of Ct

    const int t    = threadIdx.x;
    const int lane = t & 31;
    const int w    = t >> 5;                  // 0..7
    const int rh   = w >> 2;                  // row-half: rows rh*16..+15
    const int cq   = w & 3;                   // col/k quarter (32 wide)
    const int b    = blockIdx.y;
    const int q0   = blockIdx.x * BM;

    const float* Qg = Q + (size_t)(b*Lv + q0) * Dv;
    const float* Cg = C + (size_t)b * Lv * Dv;
    const unsigned char* Mg = M + (size_t)(b*Lv + q0) * Lv;
    float* attb = att + (size_t)(b*Lv + q0) * Lv;

    // ---- build Qp[d][rp] = pack(Q[2rp][d], Q[2rp+1][d]) * SCALE ----
    #pragma unroll
    for (int i = t; i < Dv*16; i += NT) {
        const int d = i >> 4, rp = i & 15;
        ull v; PACKF2(v, Qg[(2*rp)*Dv + d] * SCALE, Qg[(2*rp+1)*Dv + d] * SCALE);
        Qp[d*QPSU + rp] = v;
    }

    float psum[16];
    #pragma unroll
    for (int r = 0; r < 16; ++r) psum[r] = 0.f;
    ull acc[8][2];
    #pragma unroll
    for (int rp = 0; rp < 8; ++rp) { acc[rp][0] = 0; acc[rp][1] = 0; }

    #pragma unroll 1
    for (int kt = 0; kt < NTILE; ++kt) {
        __syncthreads();   // prev tile's ph2 done with Ct/St_t
        // ---- stage C tile via cp.async (swizzled: addr = i + (i>>6)) ----
        {
            const float* src = Cg + (size_t)kt*BK*Dv;
            #pragma unroll
            for (int j = 0; j < 32; ++j) {
                const int i = t + NT*j;
                CP_ASYNC4(ctb + (unsigned int)(i + (i >> 6))*4u, src + i);
            }
            CP_COMMIT();
            CP_WAIT0();
        }
        __syncthreads();   // tile staged

        // ---- ph1: warp (rh,cq): rows rh*16..+15, cols cq*32..+31 ----
        ull a[8];
        #pragma unroll
        for (int rp = 0; rp < 8; ++rp) a[rp] = 0;
        {
            const float* cp = Ct + (cq*32 + lane)*CTS;
            const ull* qb = Qp + rh*8;
            #pragma unroll
            for (int d = 0; d < Dv; ++d) {
                const float c = cp[d];
                ull cc; PACKF2(cc, c, c);
                const ulonglong2 qA = *(const ulonglong2*)(qb + d*QPSU);
                const ulonglong2 qB = *(const ulonglong2*)(qb + d*QPSU + 2);
                const ulonglong2 qC = *(const ulonglong2*)(qb + d*QPSU + 4);
                const ulonglong2 qD = *(const ulonglong2*)(qb + d*QPSU + 6);
                FMA2(a[0], qA.x, cc, a[0]); FMA2(a[1], qA.y, cc, a[1]);
                FMA2(a[2], qB.x, cc, a[2]); FMA2(a[3], qB.y, cc, a[3]);
                FMA2(a[4], qC.x, cc, a[4]); FMA2(a[5], qC.y, cc, a[5]);
                FMA2(a[6], qD.x, cc, a[6]); FMA2(a[7], qD.y, cc, a[7]);
            }
        }

        // ---- epilogue: exp, psum, St_t transposed store, unnorm att -> gmem ----
        {
            const int kl = cq*32 + lane;          // k within tile
            const int k  = kt*BK + kl;
            float* stp = St_t + kl*STTS + rh*16;
            #pragma unroll
            for (int q = 0; q < 4; ++q) {
                float s0, s1, s2, s3;
                UNPACKF2(s0, s1, a[2*q]);
                UNPACKF2(s2, s3, a[2*q+1]);
                const int r0 = 4*q;               // warp-local row base
                const int gr = rh*16 + r0;        // CTA row base
                float e0 = Mg[(size_t)(gr+0)*Lv + k] ? 0.f : __expf(s0);
                float e1 = Mg[(size_t)(gr+1)*Lv + k] ? 0.f : __expf(s1);
                float e2 = Mg[(size_t)(gr+2)*Lv + k] ? 0.f : __expf(s2);
                float e3 = Mg[(size_t)(gr+3)*Lv + k] ? 0.f : __expf(s3);
                psum[r0+0] += e0; psum[r0+1] += e1;
                psum[r0+2] += e2; psum[r0+3] += e3;
                *(float4*)(stp + 4*q) = make_float4(e0, e1, e2, e3);
                attb[(size_t)(gr+0)*Lv + k] = e0;
                attb[(size_t)(gr+1)*Lv + k] = e1;
                attb[(size_t)(gr+2)*Lv + k] = e2;
                attb[(size_t)(gr+3)*Lv + k] = e3;
            }
        }
        __syncthreads();   // St_t complete

        // ---- ph2: warp (rh, kq=cq): rows rh*16..+15, 64 cols, k-seg 32 ----
        {
            const float* c2p = Ct + (cq*32)*CTS + lane;
            const float* s2p = St_t + (cq*32)*STTS + rh*16;
            #pragma unroll 4
            for (int kk = 0; kk < 32; ++kk) {
                const float c0 = c2p[kk*CTS];
                const float c1 = c2p[kk*CTS + 32];
                ull cc0, cc1;
                PACKF2(cc0, c0, c0);
                PACKF2(cc1, c1, c1);
                const ulonglong2 sA = *(const ulonglong2*)(s2p + kk*STTS);
                const ulonglong2 sB = *(const ulonglong2*)(s2p + kk*STTS + 4);
                const ulonglong2 sC = *(const ulonglong2*)(s2p + kk*STTS + 8);
                const ulonglong2 sD = *(const ulonglong2*)(s2p + kk*STTS + 12);
                FMA2(acc[0][0], sA.x, cc0, acc[0][0]); FMA2(acc[0][1], sA.x, cc1, acc[0][1]);
                FMA2(acc[1][0], sA.y, cc0, acc[1][0]); FMA2(acc[1][1], sA.y, cc1, acc[1][1]);
                FMA2(acc[2][0], sB.x, cc0, acc[2][0]); FMA2(acc[2][1], sB.x, cc1, acc[2][1]);
                FMA2(acc[3][0], sB.y, cc0, acc[3][0]); FMA2(acc[3][1], sB.y, cc1, acc[3][1]);
                FMA2(acc[4][0], sC.x, cc0, acc[4][0]); FMA2(acc[4][1], sC.x, cc1, acc[4][1]);
                FMA2(acc[5][0], sC.y, cc0, acc[5][0]); FMA2(acc[5][1], sC.y, cc1, acc[5][1]);
                FMA2(acc[6][0], sD.x, cc0, acc[6][0]); FMA2(acc[6][1], sD.x, cc1, acc[6][1]);
                FMA2(acc[7][0], sD.y, cc0, acc[7][0]); FMA2(acc[7][1], sD.y, cc1, acc[7][1]);
            }
        }
    }

    // ---- row-sum reduction -> rinvs (4 cq-partials per row) ----
    #pragma unroll
    for (int r = 0; r < 16; ++r) {
        float v = psum[r];
        #pragma unroll
        for (int o = 16; o; o >>= 1) v += __shfl_xor_sync(0xffffffffu, v, o);
        if (lane == 0) sums[(rh*16 + r)*4 + cq] = v;
    }
    __syncthreads();
    if (t < BM) {
        float s = (sums[t*4+0] + sums[t*4+1]) + (sums[t*4+2] + sums[t*4+3]);
        rinvs[t] = 1.0f / s;
    }
    __syncthreads();

    // ---- out: cross-warp (kq) reduction via smem (reuse Ct: 8192 <= 8320) ----
    float* Ored = Ct;
    #pragma unroll
    for (int rp = 0; rp < 8; ++rp) {
        float lo0, hi0, lo1, hi1;
        UNPACKF2(lo0, hi0, acc[rp][0]);   // col = lane
        UNPACKF2(lo1, hi1, acc[rp][1]);   // col = lane+32
        const int gr = rh*16 + 2*rp;
        Ored[(cq*32 + gr)*64 + lane]          = lo0;
        Ored[(cq*32 + gr + 1)*64 + lane]      = hi0;
        Ored[(cq*32 + gr)*64 + lane + 32]     = lo1;
        Ored[(cq*32 + gr + 1)*64 + lane + 32] = hi1;
    }
    __syncthreads();
    #pragma unroll
    for (int i = 0; i < 8; ++i) {
        const int idx = t + NT*i;           // 0..2047
        const int row = idx >> 6, col = idx & 63;
        float v = (Ored[(0*32 + row)*64 + col] + Ored[(1*32 + row)*64 + col])
                + (Ored[(2*32 + row)*64 + col] + Ored[(3*32 + row)*64 + col]);
        out[(size_t)(b*Lv + q0 + row)*Dv + col] = v * rinvs[row];
    }

    // ---- normalize att in place (CTA owns its 32 rows) ----
    #pragma unroll
    for (int i = 0; i < 64; ++i) {
        const int idx = t + NT*i;           // 0..16383 float4
        const int row = idx >> 9, c4 = idx & 511;
        float4* p = (float4*)(attb + (size_t)row*Lv) + c4;
        float4 v = *p;
        const float rv = rinvs[row];
        v.x *= rv; v.y *= rv; v.z *= rv; v.w *= rv;
        *p = v;
    }
}

extern "C" void kernel_launch(void* const* d_in, const int* in_sizes, int n_in,
                              void* d_out, int out_size) {
    const float* Q = (const float*)d_in[0];
    const float* C = (const float*)d_in[1];
    const unsigned char* M = (const unsigned char*)d_in[2];

    float* out = (float*)d_out;                   // [B, L, D]
    float* att = out + (size_t)Bv * Lv * Dv;      // [B, L, L]

    const size_t smem_bytes = (size_t)SMEM_FLOATS * sizeof(float);  // 61,568 B
    cudaFuncSetAttribute(attn_fused_kernel,
                         cudaFuncAttributeMaxDynamicSharedMemorySize,
                         (int)smem_bytes);

    dim3 grid(Lv / BM, Bv);
    attn_fused_kernel<<<grid, NT, smem_bytes>>>(Q, C, M, out, att);
}

// round 12
// speedup vs baseline: 1.0481x; 1.0481x over previous
#include <cuda_runtime.h>
#include <math.h>

#define Bv 8
#define Lv 2048
#define Dv 64
#define BM 32            // query rows per CTA
#define BK 128           // k-tile
#define NTILE (Lv/BK)    // 16
#define NT 256           // 8 warps
#define SCALE 0.125f     // 1/sqrt(64)
#define CTSF 68          // C-tile row stride floats (17 float4-units, odd -> conflict-free)
#define STTS 36          // St_t row stride: 9 float4-units (odd) -> conflict-free
#define QPSU 18          // Qp row stride in ull

// smem floats: Ct 2*128*68=17408 + St_t 128*36=4608 + Qp 64*18*2=2304 + sums 128 + rinvs 32
#define SMEM_FLOATS (2*BK*CTSF + BK*STTS + Dv*QPSU*2 + BM*4 + BM)   // 24480 fl = 97,920 B

typedef unsigned long long ull;

#define FMA2(d_, a_, b_, c_) \
    asm("fma.rn.f32x2 %0, %1, %2, %3;" : "=l"(d_) : "l"(a_), "l"(b_), "l"(c_))
#define PACKF2(d_, x_, y_) \
    asm("mov.b64 %0, {%1, %2};" : "=l"(d_) : "f"(x_), "f"(y_))
#define UNPACKF2(x_, y_, s_) \
    asm("mov.b64 {%0, %1}, %2;" : "=f"(x_), "=f"(y_) : "l"(s_))
#define CP_ASYNC16(dst_, src_) \
    asm volatile("cp.async.cg.shared.global [%0], [%1], 16;" :: "r"(dst_), "l"(src_))
#define CP_COMMIT() asm volatile("cp.async.commit_group;")
#define CP_WAIT_ALL() asm volatile("cp.async.wait_group 0;" ::: "memory")

// ph1 inner step for one d: 1 pack + 4 LDS.128 Q + 8 FMA2
#define PH1_D(cval_, dd_) do { \
    ull cc_; PACKF2(cc_, cval_, cval_); \
    const ull* q_ = qb + (dd_)*QPSU; \
    const ulonglong2 qA_ = *(const ulonglong2*)(q_); \
    const ulonglong2 qB_ = *(const ulonglong2*)(q_ + 2); \
    const ulonglong2 qC_ = *(const ulonglong2*)(q_ + 4); \
    const ulonglong2 qD_ = *(const ulonglong2*)(q_ + 6); \
    FMA2(a[0], qA_.x, cc_, a[0]); FMA2(a[1], qA_.y, cc_, a[1]); \
    FMA2(a[2], qB_.x, cc_, a[2]); FMA2(a[3], qB_.y, cc_, a[3]); \
    FMA2(a[4], qC_.x, cc_, a[4]); FMA2(a[5], qC_.y, cc_, a[5]); \
    FMA2(a[6], qD_.x, cc_, a[6]); FMA2(a[7], qD_.y, cc_, a[7]); \
} while (0)

__global__ __launch_bounds__(NT, 2)
void attn_fused_kernel(const float* __restrict__ Q,
                       const float* __restrict__ C,
                       const unsigned char* __restrict__ M,
                       float* __restrict__ out,
                       float* __restrict__ att)
{
    extern __shared__ float smf[];
    float* Ct    = smf;                       // 2 buffers, [BK] rows of stride CTSF
    float* St_t  = Ct + 2*BK*CTSF;            // [BK][STTS] St_t[k][row 0..31]
    ull*   Qp    = (ull*)(St_t + BK*STTS);    // [Dv][QPSU] row-pair packed Q (pre-scaled)
    float* sums  = (float*)(Qp + Dv*QPSU);    // [BM][4]
    float* rinvs = sums + BM*4;               // [BM]

    const unsigned int ctb0 = (unsigned int)__cvta_generic_to_shared(Ct);
    const unsigned int ctb1 = ctb0 + BK*CTSF*4u;

    const int t    = threadIdx.x;
    const int lane = t & 31;
    const int w    = t >> 5;                  // 0..7
    const int rh   = w >> 2;                  // row-half: rows rh*16..+15
    const int cq   = w & 3;                   // col/k quarter (32 wide)
    const int b    = blockIdx.y;
    const int q0   = blockIdx.x * BM;

    const float* Qg = Q + (size_t)(b*Lv + q0) * Dv;
    const float* Cg = C + (size_t)b * Lv * Dv;
    const unsigned char* Mg = M + (size_t)(b*Lv + q0) * Lv;
    float* attb = att + (size_t)(b*Lv + q0) * Lv;

    // ---- prologue: stage tile 0 into buf0 (async), build Qp ----
    {
        const float4* s4 = (const float4*)Cg;
        #pragma unroll
        for (int j = 0; j < 8; ++j) {
            const int f = t + NT*j;           // float4 index in tile
            CP_ASYNC16(ctb0 + (unsigned int)(16*(f + (f >> 4))), s4 + f);
        }
        CP_COMMIT();
    }
    #pragma unroll
    for (int i = t; i < Dv*16; i += NT) {
        const int d = i >> 4, rp = i & 15;
        ull v; PACKF2(v, Qg[(2*rp)*Dv + d] * SCALE, Qg[(2*rp+1)*Dv + d] * SCALE);
        Qp[d*QPSU + rp] = v;
    }

    float psum[16];
    #pragma unroll
    for (int r = 0; r < 16; ++r) psum[r] = 0.f;
    ull acc[8][2];
    #pragma unroll
    for (int rp = 0; rp < 8; ++rp) { acc[rp][0] = 0; acc[rp][1] = 0; }

    #pragma unroll 1
    for (int kt = 0; kt < NTILE; ++kt) {
        CP_WAIT_ALL();       // tile kt arrived (issued prev iter / prologue)
        __syncthreads();     // staged data visible; prev ph2 done with Ct/St_t

        // ---- prefetch tile kt+1 into the other buffer (no wait) ----
        if (kt < NTILE-1) {
            const unsigned int nctb = ((kt+1) & 1) ? ctb1 : ctb0;
            const float4* s4 = (const float4*)(Cg + (size_t)(kt+1)*BK*Dv);
            #pragma unroll
            for (int j = 0; j < 8; ++j) {
                const int f = t + NT*j;
                CP_ASYNC16(nctb + (unsigned int)(16*(f + (f >> 4))), s4 + f);
            }
            CP_COMMIT();
        }

        const float* buf = Ct + (kt & 1)*BK*CTSF;

        // ---- ph1: warp (rh,cq): rows rh*16..+15, cols cq*32..+31 ----
        ull a[8];
        #pragma unroll
        for (int rp = 0; rp < 8; ++rp) a[rp] = 0;
        {
            const int kl = cq*32 + lane;
            const float4* cp4 = (const float4*)buf + kl*17;   // conflict-free LDS.128
            const ull* qb = Qp + rh*8;
            #pragma unroll
            for (int dq = 0; dq < 16; ++dq) {
                const float4 c4 = cp4[dq];
                PH1_D(c4.x, 4*dq+0);
                PH1_D(c4.y, 4*dq+1);
                PH1_D(c4.z, 4*dq+2);
                PH1_D(c4.w, 4*dq+3);
            }
        }

        // ---- epilogue: exp, psum, St_t transposed store, unnorm att -> gmem ----
        {
            const int kl = cq*32 + lane;          // k within tile
            const int k  = kt*BK + kl;
            float* stp = St_t + kl*STTS + rh*16;
            #pragma unroll
            for (int q = 0; q < 4; ++q) {
                float s0, s1, s2, s3;
                UNPACKF2(s0, s1, a[2*q]);
                UNPACKF2(s2, s3, a[2*q+1]);
                const int r0 = 4*q;
                const int gr = rh*16 + r0;
                float e0 = Mg[(size_t)(gr+0)*Lv + k] ? 0.f : __expf(s0);
                float e1 = Mg[(size_t)(gr+1)*Lv + k] ? 0.f : __expf(s1);
                float e2 = Mg[(size_t)(gr+2)*Lv + k] ? 0.f : __expf(s2);
                float e3 = Mg[(size_t)(gr+3)*Lv + k] ? 0.f : __expf(s3);
                psum[r0+0] += e0; psum[r0+1] += e1;
                psum[r0+2] += e2; psum[r0+3] += e3;
                *(float4*)(stp + 4*q) = make_float4(e0, e1, e2, e3);
                attb[(size_t)(gr+0)*Lv + k] = e0;
                attb[(size_t)(gr+1)*Lv + k] = e1;
                attb[(size_t)(gr+2)*Lv + k] = e2;
                attb[(size_t)(gr+3)*Lv + k] = e3;
            }
        }
        __syncthreads();   // St_t complete

        // ---- ph2: warp (rh, kq=cq): rows rh*16..+15, 64 cols, k-seg 32 ----
        {
            const float* c2p = buf + (cq*32)*CTSF + lane;     // row-contiguous reads
            const float* s2p = St_t + (cq*32)*STTS + rh*16;
            #pragma unroll 4
            for (int kk = 0; kk < 32; ++kk) {
                const float c0 = c2p[kk*CTSF];
                const float c1 = c2p[kk*CTSF + 32];
                ull cc0, cc1;
                PACKF2(cc0, c0, c0);
                PACKF2(cc1, c1, c1);
                const ulonglong2 sA = *(const ulonglong2*)(s2p + kk*STTS);
                const ulonglong2 sB = *(const ulonglong2*)(s2p + kk*STTS + 4);
                const ulonglong2 sC = *(const ulonglong2*)(s2p + kk*STTS + 8);
                const ulonglong2 sD = *(const ulonglong2*)(s2p + kk*STTS + 12);
                FMA2(acc[0][0], sA.x, cc0, acc[0][0]); FMA2(acc[0][1], sA.x, cc1, acc[0][1]);
                FMA2(acc[1][0], sA.y, cc0, acc[1][0]); FMA2(acc[1][1], sA.y, cc1, acc[1][1]);
                FMA2(acc[2][0], sB.x, cc0, acc[2][0]); FMA2(acc[2][1], sB.x, cc1, acc[2][1]);
                FMA2(acc[3][0], sB.y, cc0, acc[3][0]); FMA2(acc[3][1], sB.y, cc1, acc[3][1]);
                FMA2(acc[4][0], sC.x, cc0, acc[4][0]); FMA2(acc[4][1], sC.x, cc1, acc[4][1]);
                FMA2(acc[5][0], sC.y, cc0, acc[5][0]); FMA2(acc[5][1], sC.y, cc1, acc[5][1]);
                FMA2(acc[6][0], sD.x, cc0, acc[6][0]); FMA2(acc[6][1], sD.x, cc1, acc[6][1]);
                FMA2(acc[7][0], sD.y, cc0, acc[7][0]); FMA2(acc[7][1], sD.y, cc1, acc[7][1]);
            }
        }
    }

    // ---- row-sum reduction -> rinvs (4 cq-partials per row) ----
    #pragma unroll
    for (int r = 0; r < 16; ++r) {
        float v = psum[r];
        #pragma unroll
        for (int o = 16; o; o >>= 1) v += __shfl_xor_sync(0xffffffffu, v, o);
        if (lane == 0) sums[(rh*16 + r)*4 + cq] = v;
    }
    __syncthreads();
    if (t < BM) {
        float s = (sums[t*4+0] + sums[t*4+1]) + (sums[t*4+2] + sums[t*4+3]);
        rinvs[t] = 1.0f / s;
    }
    __syncthreads();

    // ---- out: cross-warp (kq) reduction via smem (reuse Ct: 8192 <= 17408) ----
    float* Ored = Ct;
    #pragma unroll
    for (int rp = 0; rp < 8; ++rp) {
        float lo0, hi0, lo1, hi1;
        UNPACKF2(lo0, hi0, acc[rp][0]);   // col = lane
        UNPACKF2(lo1, hi1, acc[rp][1]);   // col = lane+32
        const int gr = rh*16 + 2*rp;
        Ored[(cq*32 + gr)*64 + lane]          = lo0;
        Ored[(cq*32 + gr + 1)*64 + lane]      = hi0;
        Ored[(cq*32 + gr)*64 + lane + 32]     = lo1;
        Ored[(cq*32 + gr + 1)*64 + lane + 32] = hi1;
    }
    __syncthreads();
    #pragma unroll
    for (int i = 0; i < 8; ++i) {
        const int idx = t + NT*i;           // 0..2047
        const int row = idx >> 6, col = idx & 63;
        float v = (Ored[(0*32 + row)*64 + col] + Ored[(1*32 + row)*64 + col])
                + (Ored[(2*32 + row)*64 + col] + Ored[(3*32 + row)*64 + col]);
        out[(size_t)(b*Lv + q0 + row)*Dv + col] = v * rinvs[row];
    }

    // ---- normalize att in place (CTA owns its 32 rows) ----
    #pragma unroll
    for (int i = 0; i < 64; ++i) {
        const int idx = t + NT*i;           // 0..16383 float4
        const int row = idx >> 9, c4 = idx & 511;
        float4* p = (float4*)(attb + (size_t)row*Lv) + c4;
        float4 v = *p;
        const float rv = rinvs[row];
        v.x *= rv; v.y *= rv; v.z *= rv; v.w *= rv;
        *p = v;
    }
}

extern "C" void kernel_launch(void* const* d_in, const int* in_sizes, int n_in,
                              void* d_out, int out_size) {
    const float* Q = (const float*)d_in[0];
    const float* C = (const float*)d_in[1];
    const unsigned char* M = (const unsigned char*)d_in[2];

    float* out = (float*)d_out;                   // [B, L, D]
    float* att = out + (size_t)Bv * Lv * Dv;      // [B, L, L]

    const size_t smem_bytes = (size_t)SMEM_FLOATS * sizeof(float);  // 97,920 B
    cudaFuncSetAttribute(attn_fused_kernel,
                         cudaFuncAttributeMaxDynamicSharedMemorySize,
                         (int)smem_bytes);

    dim3 grid(Lv / BM, Bv);
    attn_fused_kernel<<<grid, NT, smem_bytes>>>(Q, C, M, out, att);
}

// round 13
// speedup vs baseline: 1.2617x; 1.2038x over previous
#include <cuda_runtime.h>
#include <math.h>

#define Bv 8
#define Lv 2048
#define Dv 64
#define BM 32            // query rows per CTA
#define BK 256           // k-tile
#define NTILE (Lv/BK)    // 8
#define NT 256           // 8 warps
#define SCALE 0.125f     // 1/sqrt(64)
#define STTS 36          // St_t row stride: 9 float4-units (odd) -> conflict-free
#define QPSU 16          // Qp row stride in ull (broadcast reads: stride parity irrelevant)

// smem floats: Ct 256*64=16384 (XOR-swizzled) + St_t 256*36=9216 + Qp 64*16*2=2048
//            + sums 128 + rinvs 32  = 27808 floats = 111,232 B  (2 CTAs/SM)
#define SMEM_FLOATS (BK*Dv + BK*STTS + Dv*QPSU*2 + BM*4 + BM)

typedef unsigned long long ull;

#define FMA2(d_, a_, b_, c_) \
    asm("fma.rn.f32x2 %0, %1, %2, %3;" : "=l"(d_) : "l"(a_), "l"(b_), "l"(c_))
#define PACKF2(d_, x_, y_) \
    asm("mov.b64 %0, {%1, %2};" : "=l"(d_) : "f"(x_), "f"(y_))
#define UNPACKF2(x_, y_, s_) \
    asm("mov.b64 {%0, %1}, %2;" : "=f"(x_), "=f"(y_) : "l"(s_))

// ph1 step for one d: 2 packs + 4 broadcast LDS.128 (Q) + 16 FMA2 (16 rows x 64 cols)
#define PH1_D2(c0_, c1_, dd_) do { \
    ull cc0_, cc1_; \
    PACKF2(cc0_, c0_, c0_); \
    PACKF2(cc1_, c1_, c1_); \
    const ull* q_ = qb + (dd_)*QPSU; \
    const ulonglong2 qA_ = *(const ulonglong2*)(q_); \
    const ulonglong2 qB_ = *(const ulonglong2*)(q_ + 2); \
    const ulonglong2 qC_ = *(const ulonglong2*)(q_ + 4); \
    const ulonglong2 qD_ = *(const ulonglong2*)(q_ + 6); \
    FMA2(a0[0], qA_.x, cc0_, a0[0]); FMA2(a1[0], qA_.x, cc1_, a1[0]); \
    FMA2(a0[1], qA_.y, cc0_, a0[1]); FMA2(a1[1], qA_.y, cc1_, a1[1]); \
    FMA2(a0[2], qB_.x, cc0_, a0[2]); FMA2(a1[2], qB_.x, cc1_, a1[2]); \
    FMA2(a0[3], qB_.y, cc0_, a0[3]); FMA2(a1[3], qB_.y, cc1_, a1[3]); \
    FMA2(a0[4], qC_.x, cc0_, a0[4]); FMA2(a1[4], qC_.x, cc1_, a1[4]); \
    FMA2(a0[5], qC_.y, cc0_, a0[5]); FMA2(a1[5], qC_.y, cc1_, a1[5]); \
    FMA2(a0[6], qD_.x, cc0_, a0[6]); FMA2(a1[6], qD_.x, cc1_, a1[6]); \
    FMA2(a0[7], qD_.y, cc0_, a0[7]); FMA2(a1[7], qD_.y, cc1_, a1[7]); \
} while (0)

__global__ __launch_bounds__(NT, 2)
void attn_fused_kernel(const float* __restrict__ Q,
                       const float* __restrict__ C,
                       const unsigned char* __restrict__ M,
                       float* __restrict__ out,
                       float* __restrict__ att)
{
    extern __shared__ float smf[];
    float* Ct    = smf;                       // [BK*Dv] XOR-swizzled C tile
    float* St_t  = Ct + BK*Dv;                // [BK][STTS] St_t[k][row 0..31]
    ull*   Qp    = (ull*)(St_t + BK*STTS);    // [Dv][QPSU] row-pair packed Q (pre-scaled)
    float* sums  = (float*)(Qp + Dv*QPSU);    // [BM][4]
    float* rinvs = sums + BM*4;               // [BM]

    const int t    = threadIdx.x;
    const int lane = t & 31;
    const int w    = t >> 5;                  // 0..7
    const int rh   = w >> 2;                  // row-half: rows rh*16..+15
    const int cq   = w & 3;                   // col/k quarter (64 wide)
    const int b    = blockIdx.y;
    const int q0   = blockIdx.x * BM;

    const float* Qg = Q + (size_t)(b*Lv + q0) * Dv;
    const float* Cg = C + (size_t)b * Lv * Dv;
    const unsigned char* Mg = M + (size_t)(b*Lv + q0) * Lv;
    float* attb = att + (size_t)(b*Lv + q0) * Lv;

    // ---- build Qp[d][rp] = pack(Q[2rp][d], Q[2rp+1][d]) * SCALE ----
    #pragma unroll
    for (int i = t; i < Dv*16; i += NT) {
        const int d = i >> 4, rp = i & 15;
        ull v; PACKF2(v, Qg[(2*rp)*Dv + d] * SCALE, Qg[(2*rp+1)*Dv + d] * SCALE);
        Qp[d*QPSU + rp] = v;
    }

    float psum[16];
    #pragma unroll
    for (int r = 0; r < 16; ++r) psum[r] = 0.f;
    ull acc[8][2];
    #pragma unroll
    for (int rp = 0; rp < 8; ++rp) { acc[rp][0] = 0; acc[rp][1] = 0; }

    #pragma unroll 1
    for (int kt = 0; kt < NTILE; ++kt) {
        __syncthreads();   // prev tile's ph2 done with Ct/St_t
        // ---- stage C tile, XOR-swizzled, vectorized: 16 LDG.128 + 16 STS.128 ----
        // float4 unit u = (f & ~15) | ((f ^ (f>>4)) & 15)   (= k*16 + (dq ^ (k&15)))
        {
            const float4* src4 = (const float4*)(Cg + (size_t)kt*BK*Dv);
            #pragma unroll
            for (int h = 0; h < 2; ++h) {
                float4 rr[8];
                #pragma unroll
                for (int j = 0; j < 8; ++j) rr[j] = src4[t + NT*(h*8 + j)];
                #pragma unroll
                for (int j = 0; j < 8; ++j) {
                    const int f = t + NT*(h*8 + j);
                    const int u = (f & ~15) | ((f ^ (f >> 4)) & 15);
                    ((float4*)Ct)[u] = rr[j];
                }
            }
        }
        __syncthreads();   // staged

        // ---- ph1: warp (rh,cq): rows rh*16..+15, cols cq*64..+63 ----
        ull a0[8], a1[8];
        #pragma unroll
        for (int rp = 0; rp < 8; ++rp) { a0[rp] = 0; a1[rp] = 0; }
        {
            const int k0 = cq*64 + lane;          // col block 0 (block 1 = k0+32)
            const int mlane = lane & 15;          // (k0&15) == ((k0+32)&15)
            const float4* cta4 = (const float4*)Ct + (k0 << 4);
            const float4* ctb4 = cta4 + (32 << 4);
            const ull* qb = Qp + rh*8;
            #pragma unroll
            for (int dq = 0; dq < 16; ++dq) {
                const int off = dq ^ mlane;
                const float4 ca = cta4[off];      // conflict-free LDS.128
                const float4 cb = ctb4[off];
                PH1_D2(ca.x, cb.x, 4*dq+0);
                PH1_D2(ca.y, cb.y, 4*dq+1);
                PH1_D2(ca.z, cb.z, 4*dq+2);
                PH1_D2(ca.w, cb.w, 4*dq+3);
            }
        }

        // ---- epilogue: exp, psum, St_t transposed store, unnorm att -> gmem ----
        #pragma unroll
        for (int cb = 0; cb < 2; ++cb) {
            const int kl = cq*64 + cb*32 + lane;  // k within tile
            const int k  = kt*BK + kl;
            float* stp = St_t + kl*STTS + rh*16;
            #pragma unroll
            for (int q = 0; q < 4; ++q) {
                float s0, s1, s2, s3;
                if (cb == 0) { UNPACKF2(s0, s1, a0[2*q]); UNPACKF2(s2, s3, a0[2*q+1]); }
                else         { UNPACKF2(s0, s1, a1[2*q]); UNPACKF2(s2, s3, a1[2*q+1]); }
                const int r0 = 4*q;
                const int gr = rh*16 + r0;
                float e0 = Mg[(size_t)(gr+0)*Lv + k] ? 0.f : __expf(s0);
                float e1 = Mg[(size_t)(gr+1)*Lv + k] ? 0.f : __expf(s1);
                float e2 = Mg[(size_t)(gr+2)*Lv + k] ? 0.f : __expf(s2);
                float e3 = Mg[(size_t)(gr+3)*Lv + k] ? 0.f : __expf(s3);
                psum[r0+0] += e0; psum[r0+1] += e1;
                psum[r0+2] += e2; psum[r0+3] += e3;
                *(float4*)(stp + 4*q) = make_float4(e0, e1, e2, e3);
                attb[(size_t)(gr+0)*Lv + k] = e0;
                attb[(size_t)(gr+1)*Lv + k] = e1;
                attb[(size_t)(gr+2)*Lv + k] = e2;
                attb[(size_t)(gr+3)*Lv + k] = e3;
            }
        }
        __syncthreads();   // St_t complete

        // ---- ph2: warp (rh, kq=cq): rows rh*16..+15, 64 cols, k-seg 64 ----
        {
            const int l3 = lane & 3;
            const int p4 = (lane >> 2) << 2;      // 4*(lane>>2)
            #pragma unroll 1
            for (int kb = 0; kb < 4; ++kb) {
                const int kbase = cq*64 + kb*16;  // k&15 == kk below
                const float* s2p = St_t + kbase*STTS + rh*16;
                #pragma unroll
                for (int kk = 0; kk < 16; ++kk) {
                    const int i0 = ((kbase + kk) << 6) + (p4 ^ (kk << 2)) + l3;
                    const float c0 = Ct[i0];          // conflict-free
                    const float c1 = Ct[i0 ^ 32];     // d = lane+32 (unit ^ 8)
                    ull cc0, cc1;
                    PACKF2(cc0, c0, c0);
                    PACKF2(cc1, c1, c1);
                    const ull* sp = (const ull*)(s2p + kk*STTS);
                    const ulonglong2 sA = *(const ulonglong2*)(sp);
                    const ulonglong2 sB = *(const ulonglong2*)(sp + 2);
                    const ulonglong2 sC = *(const ulonglong2*)(sp + 4);
                    const ulonglong2 sD = *(const ulonglong2*)(sp + 6);
                    FMA2(acc[0][0], sA.x, cc0, acc[0][0]); FMA2(acc[0][1], sA.x, cc1, acc[0][1]);
                    FMA2(acc[1][0], sA.y, cc0, acc[1][0]); FMA2(acc[1][1], sA.y, cc1, acc[1][1]);
                    FMA2(acc[2][0], sB.x, cc0, acc[2][0]); FMA2(acc[2][1], sB.x, cc1, acc[2][1]);
                    FMA2(acc[3][0], sB.y, cc0, acc[3][0]); FMA2(acc[3][1], sB.y, cc1, acc[3][1]);
                    FMA2(acc[4][0], sC.x, cc0, acc[4][0]); FMA2(acc[4][1], sC.x, cc1, acc[4][1]);
                    FMA2(acc[5][0], sC.y, cc0, acc[5][0]); FMA2(acc[5][1], sC.y, cc1, acc[5][1]);
                    FMA2(acc[6][0], sD.x, cc0, acc[6][0]); FMA2(acc[6][1], sD.x, cc1, acc[6][1]);
                    FMA2(acc[7][0], sD.y, cc0, acc[7][0]); FMA2(acc[7][1], sD.y, cc1, acc[7][1]);
                }
            }
        }
    }

    // ---- row-sum reduction -> rinvs (4 cq-partials per row) ----
    #pragma unroll
    for (int r = 0; r < 16; ++r) {
        float v = psum[r];
        #pragma unroll
        for (int o = 16; o; o >>= 1) v += __shfl_xor_sync(0xffffffffu, v, o);
        if (lane == 0) sums[(rh*16 + r)*4 + cq] = v;
    }
    __syncthreads();
    if (t < BM) {
        float s = (sums[t*4+0] + sums[t*4+1]) + (sums[t*4+2] + sums[t*4+3]);
        rinvs[t] = 1.0f / s;
    }
    __syncthreads();

    // ---- out: cross-warp (kq) reduction via smem (reuse Ct: 8192 <= 16384) ----
    float* Ored = Ct;
    #pragma unroll
    for (int rp = 0; rp < 8; ++rp) {
        float lo0, hi0, lo1, hi1;
        UNPACKF2(lo0, hi0, acc[rp][0]);   // col = lane
        UNPACKF2(lo1, hi1, acc[rp][1]);   // col = lane+32
        const int gr = rh*16 + 2*rp;
        Ored[(cq*32 + gr)*64 + lane]          = lo0;
        Ored[(cq*32 + gr + 1)*64 + lane]      = hi0;
        Ored[(cq*32 + gr)*64 + lane + 32]     = lo1;
        Ored[(cq*32 + gr + 1)*64 + lane + 32] = hi1;
    }
    __syncthreads();
    #pragma unroll
    for (int i = 0; i < 8; ++i) {
        const int idx = t + NT*i;           // 0..2047
        const int row = idx >> 6, col = idx & 63;
        float v = (Ored[(0*32 + row)*64 + col] + Ored[(1*32 + row)*64 + col])
                + (Ored[(2*32 + row)*64 + col] + Ored[(3*32 + row)*64 + col]);
        out[(size_t)(b*Lv + q0 + row)*Dv + col] = v * rinvs[row];
    }

    // ---- normalize att in place (CTA owns its 32 rows) ----
    #pragma unroll
    for (int i = 0; i < 64; ++i) {
        const int idx = t + NT*i;           // 0..16383 float4
        const int row = idx >> 9, c4 = idx & 511;
        float4* p = (float4*)(attb + (size_t)row*Lv) + c4;
        float4 v = *p;
        const float rv = rinvs[row];
        v.x *= rv; v.y *= rv; v.z *= rv; v.w *= rv;
        *p = v;
    }
}

extern "C" void kernel_launch(void* const* d_in, const int* in_sizes, int n_in,
                              void* d_out, int out_size) {
    const float* Q = (const float*)d_in[0];
    const float* C = (const float*)d_in[1];
    const unsigned char* M = (const unsigned char*)d_in[2];

    float* out = (float*)d_out;                   // [B, L, D]
    float* att = out + (size_t)Bv * Lv * Dv;      // [B, L, L]

    const size_t smem_bytes = (size_t)SMEM_FLOATS * sizeof(float);  // 111,232 B
    cudaFuncSetAttribute(attn_fused_kernel,
                         cudaFuncAttributeMaxDynamicSharedMemorySize,
                         (int)smem_bytes);

    dim3 grid(Lv / BM, Bv);
    attn_fused_kernel<<<grid, NT, smem_bytes>>>(Q, C, M, out, att);
}

// round 14
// speedup vs baseline: 1.2621x; 1.0003x over previous
#include <cuda_runtime.h>
#include <math.h>

#define Bv 8
#define Lv 2048
#define Dv 64
#define BM 32            // query rows per CTA
#define BK 256           // k-tile
#define NTILE (Lv/BK)    // 8
#define NT 256           // 8 warps
#define SCALE 0.125f     // 1/sqrt(64)
#define STTS 36          // St_t row stride: 9 float4-units (odd) -> conflict-free
#define QPSU 16          // Qp row stride in ull (broadcast reads: stride parity irrelevant)

// smem floats: Ct 256*64=16384 (XOR-swizzled) + St_t 256*36=9216 + Qp 64*16*2=2048
//            + sums 128 + rinvs 32  = 27808 floats = 111,232 B  (2 CTAs/SM)
#define SMEM_FLOATS (BK*Dv + BK*STTS + Dv*QPSU*2 + BM*4 + BM)

typedef unsigned long long ull;

#define FMA2(d_, a_, b_, c_) \
    asm("fma.rn.f32x2 %0, %1, %2, %3;" : "=l"(d_) : "l"(a_), "l"(b_), "l"(c_))
#define PACKF2(d_, x_, y_) \
    asm("mov.b64 %0, {%1, %2};" : "=l"(d_) : "f"(x_), "f"(y_))
#define UNPACKF2(x_, y_, s_) \
    asm("mov.b64 {%0, %1}, %2;" : "=f"(x_), "=f"(y_) : "l"(s_))

// ph1 step for one d: 2 packs + 4 broadcast LDS.128 (Q) + 16 FMA2 (16 rows x 64 cols)
#define PH1_D2(c0_, c1_, dd_) do { \
    ull cc0_, cc1_; \
    PACKF2(cc0_, c0_, c0_); \
    PACKF2(cc1_, c1_, c1_); \
    const ull* q_ = qb + (dd_)*QPSU; \
    const ulonglong2 qA_ = *(const ulonglong2*)(q_); \
    const ulonglong2 qB_ = *(const ulonglong2*)(q_ + 2); \
    const ulonglong2 qC_ = *(const ulonglong2*)(q_ + 4); \
    const ulonglong2 qD_ = *(const ulonglong2*)(q_ + 6); \
    FMA2(a0[0], qA_.x, cc0_, a0[0]); FMA2(a1[0], qA_.x, cc1_, a1[0]); \
    FMA2(a0[1], qA_.y, cc0_, a0[1]); FMA2(a1[1], qA_.y, cc1_, a1[1]); \
    FMA2(a0[2], qB_.x, cc0_, a0[2]); FMA2(a1[2], qB_.x, cc1_, a1[2]); \
    FMA2(a0[3], qB_.y, cc0_, a0[3]); FMA2(a1[3], qB_.y, cc1_, a1[3]); \
    FMA2(a0[4], qC_.x, cc0_, a0[4]); FMA2(a1[4], qC_.x, cc1_, a1[4]); \
    FMA2(a0[5], qC_.y, cc0_, a0[5]); FMA2(a1[5], qC_.y, cc1_, a1[5]); \
    FMA2(a0[6], qD_.x, cc0_, a0[6]); FMA2(a1[6], qD_.x, cc1_, a1[6]); \
    FMA2(a0[7], qD_.y, cc0_, a0[7]); FMA2(a1[7], qD_.y, cc1_, a1[7]); \
} while (0)

__global__ __launch_bounds__(NT, 2)
void attn_fused_kernel(const float* __restrict__ Q,
                       const float* __restrict__ C,
                       const unsigned char* __restrict__ M,
                       float* __restrict__ out,
                       float* __restrict__ att)
{
    extern __shared__ float smf[];
    float* Ct    = smf;                       // [BK*Dv] XOR-swizzled C tile
    float* St_t  = Ct + BK*Dv;                // [BK][STTS] St_t[k][row 0..31]
    ull*   Qp    = (ull*)(St_t + BK*STTS);    // [Dv][QPSU] row-pair packed Q (pre-scaled)
    float* sums  = (float*)(Qp + Dv*QPSU);    // [BM][4]
    float* rinvs = sums + BM*4;               // [BM]

    const int t    = threadIdx.x;
    const int lane = t & 31;
    const int w    = t >> 5;                  // 0..7
    const int rh   = w >> 2;                  // row-half: rows rh*16..+15
    const int cq   = w & 3;                   // col/k quarter (64 wide)
    const int b    = blockIdx.y;
    const int q0   = blockIdx.x * BM;

    const float* Qg = Q + (size_t)(b*Lv + q0) * Dv;
    const float* Cg = C + (size_t)b * Lv * Dv;
    const unsigned char* Mg = M + (size_t)(b*Lv + q0) * Lv;
    float* attb = att + (size_t)(b*Lv + q0) * Lv;

    // ---- build Qp[d][rp] = pack(Q[2rp][d], Q[2rp+1][d]) * SCALE ----
    #pragma unroll
    for (int i = t; i < Dv*16; i += NT) {
        const int d = i >> 4, rp = i & 15;
        ull v; PACKF2(v, Qg[(2*rp)*Dv + d] * SCALE, Qg[(2*rp+1)*Dv + d] * SCALE);
        Qp[d*QPSU + rp] = v;
    }

    float psum[16];
    #pragma unroll
    for (int r = 0; r < 16; ++r) psum[r] = 0.f;
    ull acc[8][2];
    #pragma unroll
    for (int rp = 0; rp < 8; ++rp) { acc[rp][0] = 0; acc[rp][1] = 0; }

    #pragma unroll 1
    for (int kt = 0; kt < NTILE; ++kt) {
        __syncthreads();   // prev tile's ph2 done with Ct/St_t
        // ---- stage C tile, XOR-swizzled, vectorized: 16 LDG.128 + 16 STS.128 ----
        // float4 unit u = (f & ~15) | ((f ^ (f>>4)) & 15)   (= k*16 + (dq ^ (k&15)))
        {
            const float4* src4 = (const float4*)(Cg + (size_t)kt*BK*Dv);
            #pragma unroll
            for (int h = 0; h < 2; ++h) {
                float4 rr[8];
                #pragma unroll
                for (int j = 0; j < 8; ++j) rr[j] = src4[t + NT*(h*8 + j)];
                #pragma unroll
                for (int j = 0; j < 8; ++j) {
                    const int f = t + NT*(h*8 + j);
                    const int u = (f & ~15) | ((f ^ (f >> 4)) & 15);
                    ((float4*)Ct)[u] = rr[j];
                }
            }
        }
        __syncthreads();   // staged

        // ---- ph1: warp (rh,cq): rows rh*16..+15, cols cq*64..+63 ----
        ull a0[8], a1[8];
        #pragma unroll
        for (int rp = 0; rp < 8; ++rp) { a0[rp] = 0; a1[rp] = 0; }
        {
            const int k0 = cq*64 + lane;          // col block 0 (block 1 = k0+32)
            const int mlane = lane & 15;          // (k0&15) == ((k0+32)&15)
            const float4* cta4 = (const float4*)Ct + (k0 << 4);
            const float4* ctb4 = cta4 + (32 << 4);
            const ull* qb = Qp + rh*8;
            #pragma unroll
            for (int dq = 0; dq < 16; ++dq) {
                const int off = dq ^ mlane;
                const float4 ca = cta4[off];      // conflict-free LDS.128
                const float4 cb = ctb4[off];
                PH1_D2(ca.x, cb.x, 4*dq+0);
                PH1_D2(ca.y, cb.y, 4*dq+1);
                PH1_D2(ca.z, cb.z, 4*dq+2);
                PH1_D2(ca.w, cb.w, 4*dq+3);
            }
        }

        // ---- epilogue: exp, psum, St_t transposed store, unnorm att -> gmem ----
        #pragma unroll
        for (int cb = 0; cb < 2; ++cb) {
            const int kl = cq*64 + cb*32 + lane;  // k within tile
            const int k  = kt*BK + kl;
            float* stp = St_t + kl*STTS + rh*16;
            #pragma unroll
            for (int q = 0; q < 4; ++q) {
                float s0, s1, s2, s3;
                if (cb == 0) { UNPACKF2(s0, s1, a0[2*q]); UNPACKF2(s2, s3, a0[2*q+1]); }
                else         { UNPACKF2(s0, s1, a1[2*q]); UNPACKF2(s2, s3, a1[2*q+1]); }
                const int r0 = 4*q;
                const int gr = rh*16 + r0;
                float e0 = Mg[(size_t)(gr+0)*Lv + k] ? 0.f : __expf(s0);
                float e1 = Mg[(size_t)(gr+1)*Lv + k] ? 0.f : __expf(s1);
                float e2 = Mg[(size_t)(gr+2)*Lv + k] ? 0.f : __expf(s2);
                float e3 = Mg[(size_t)(gr+3)*Lv + k] ? 0.f : __expf(s3);
                psum[r0+0] += e0; psum[r0+1] += e1;
                psum[r0+2] += e2; psum[r0+3] += e3;
                *(float4*)(stp + 4*q) = make_float4(e0, e1, e2, e3);
                attb[(size_t)(gr+0)*Lv + k] = e0;
                attb[(size_t)(gr+1)*Lv + k] = e1;
                attb[(size_t)(gr+2)*Lv + k] = e2;
                attb[(size_t)(gr+3)*Lv + k] = e3;
            }
        }
        __syncthreads();   // St_t complete

        // ---- ph2: warp (rh, kq=cq): rows rh*16..+15, 64 cols, k-seg 64 ----
        {
            const int l3 = lane & 3;
            const int p4 = (lane >> 2) << 2;      // 4*(lane>>2)
            #pragma unroll 1
            for (int kb = 0; kb < 4; ++kb) {
                const int kbase = cq*64 + kb*16;  // k&15 == kk below
                const float* s2p = St_t + kbase*STTS + rh*16;
                #pragma unroll
                for (int kk = 0; kk < 16; ++kk) {
                    const int i0 = ((kbase + kk) << 6) + (p4 ^ (kk << 2)) + l3;
                    const float c0 = Ct[i0];          // conflict-free
                    const float c1 = Ct[i0 ^ 32];     // d = lane+32 (unit ^ 8)
                    ull cc0, cc1;
                    PACKF2(cc0, c0, c0);
                    PACKF2(cc1, c1, c1);
                    const ull* sp = (const ull*)(s2p + kk*STTS);
                    const ulonglong2 sA = *(const ulonglong2*)(sp);
                    const ulonglong2 sB = *(const ulonglong2*)(sp + 2);
                    const ulonglong2 sC = *(const ulonglong2*)(sp + 4);
                    const ulonglong2 sD = *(const ulonglong2*)(sp + 6);
                    FMA2(acc[0][0], sA.x, cc0, acc[0][0]); FMA2(acc[0][1], sA.x, cc1, acc[0][1]);
                    FMA2(acc[1][0], sA.y, cc0, acc[1][0]); FMA2(acc[1][1], sA.y, cc1, acc[1][1]);
                    FMA2(acc[2][0], sB.x, cc0, acc[2][0]); FMA2(acc[2][1], sB.x, cc1, acc[2][1]);
                    FMA2(acc[3][0], sB.y, cc0, acc[3][0]); FMA2(acc[3][1], sB.y, cc1, acc[3][1]);
                    FMA2(acc[4][0], sC.x, cc0, acc[4][0]); FMA2(acc[4][1], sC.x, cc1, acc[4][1]);
                    FMA2(acc[5][0], sC.y, cc0, acc[5][0]); FMA2(acc[5][1], sC.y, cc1, acc[5][1]);
                    FMA2(acc[6][0], sD.x, cc0, acc[6][0]); FMA2(acc[6][1], sD.x, cc1, acc[6][1]);
                    FMA2(acc[7][0], sD.y, cc0, acc[7][0]); FMA2(acc[7][1], sD.y, cc1, acc[7][1]);
                }
            }
        }
    }

    // ---- row-sum reduction -> rinvs (4 cq-partials per row) ----
    #pragma unroll
    for (int r = 0; r < 16; ++r) {
        float v = psum[r];
        #pragma unroll
        for (int o = 16; o; o >>= 1) v += __shfl_xor_sync(0xffffffffu, v, o);
        if (lane == 0) sums[(rh*16 + r)*4 + cq] = v;
    }
    __syncthreads();
    if (t < BM) {
        float s = (sums[t*4+0] + sums[t*4+1]) + (sums[t*4+2] + sums[t*4+3]);
        rinvs[t] = 1.0f / s;
    }
    __syncthreads();

    // ---- out: cross-warp (kq) reduction via smem (reuse Ct: 8192 <= 16384) ----
    float* Ored = Ct;
    #pragma unroll
    for (int rp = 0; rp < 8; ++rp) {
        float lo0, hi0, lo1, hi1;
        UNPACKF2(lo0, hi0, acc[rp][0]);   // col = lane
        UNPACKF2(lo1, hi1, acc[rp][1]);   // col = lane+32
        const int gr = rh*16 + 2*rp;
        Ored[(cq*32 + gr)*64 + lane]          = lo0;
        Ored[(cq*32 + gr + 1)*64 + lane]      = hi0;
        Ored[(cq*32 + gr)*64 + lane + 32]     = lo1;
        Ored[(cq*32 + gr + 1)*64 + lane + 32] = hi1;
    }
    __syncthreads();
    #pragma unroll
    for (int i = 0; i < 8; ++i) {
        const int idx = t + NT*i;           // 0..2047
        const int row = idx >> 6, col = idx & 63;
        float v = (Ored[(0*32 + row)*64 + col] + Ored[(1*32 + row)*64 + col])
                + (Ored[(2*32 + row)*64 + col] + Ored[(3*32 + row)*64 + col]);
        out[(size_t)(b*Lv + q0 + row)*Dv + col] = v * rinvs[row];
    }

    // ---- normalize att in place (CTA owns its 32 rows) ----
    #pragma unroll
    for (int i = 0; i < 64; ++i) {
        const int idx = t + NT*i;           // 0..16383 float4
        const int row = idx >> 9, c4 = idx & 511;
        float4* p = (float4*)(attb + (size_t)row*Lv) + c4;
        float4 v = *p;
        const float rv = rinvs[row];
        v.x *= rv; v.y *= rv; v.z *= rv; v.w *= rv;
        *p = v;
    }
}

extern "C" void kernel_launch(void* const* d_in, const int* in_sizes, int n_in,
                              void* d_out, int out_size) {
    const float* Q = (const float*)d_in[0];
    const float* C = (const float*)d_in[1];
    const unsigned char* M = (const unsigned char*)d_in[2];

    float* out = (float*)d_out;                   // [B, L, D]
    float* att = out + (size_t)Bv * Lv * Dv;      // [B, L, L]

    const size_t smem_bytes = (size_t)SMEM_FLOATS * sizeof(float);  // 111,232 B
    cudaFuncSetAttribute(attn_fused_kernel,
                         cudaFuncAttributeMaxDynamicSharedMemorySize,
                         (int)smem_bytes);

    dim3 grid(Lv / BM, Bv);
    attn_fused_kernel<<<grid, NT, smem_bytes>>>(Q, C, M, out, att);
}

// round 16
// speedup vs baseline: 2.2141x; 1.7543x over previous
#include <cuda_runtime.h>
#include <cuda_bf16.h>
#include <math.h>
#include <stdint.h>

#define Bv 8
#define Lv 2048
#define Dv 64
#define BM 32            // query rows per CTA
#define BK 256           // k-tile (seq)
#define NTILE (Lv/BK)    // 8
#define NT 256           // 8 warps = 2 row-halves x 4 seq-quarters
#define SCALE 0.125f

#define CW 36            // C-tile row stride in u32 words (mod 32 == 4 -> conflict-free)
#define SM_CHI  0
#define SM_CLO  (256*CW)            // 9216
#define SM_SUMS (2*256*CW)          // 18432 (float words)
#define SM_RINV (SM_SUMS + 128)
#define SMEM_WORDS (SM_RINV + 32)   // 18592 words = 74368 B -> 2 CTAs/SM

// pack 2 fp32 -> bf16x2 (lower half = lo_, upper = hi_)
#define PACKB(d_, lo_, hi_) \
    asm("cvt.rn.bf16x2.f32 %0, %1, %2;" : "=r"(d_) : "f"(hi_), "f"(lo_))

// D += A(bf16x2 x4) * B(bf16x2 x2)   [m16n8k16 row.col]
#define MMA(d_, a_, b0_, b1_) \
    asm volatile("mma.sync.aligned.m16n8k16.row.col.f32.bf16.bf16.f32 " \
        "{%0,%1,%2,%3}, {%4,%5,%6,%7}, {%8,%9}, {%0,%1,%2,%3};" \
        : "+f"((d_)[0]), "+f"((d_)[1]), "+f"((d_)[2]), "+f"((d_)[3]) \
        : "r"((a_)[0]), "r"((a_)[1]), "r"((a_)[2]), "r"((a_)[3]), \
          "r"(b0_), "r"(b1_))

__device__ __forceinline__ void split_pack(float x, float y,
                                           uint32_t& hi, uint32_t& lo) {
    PACKB(hi, x, y);
    const float hx = __uint_as_float(hi << 16);
    const float hy = __uint_as_float(hi & 0xffff0000u);
    PACKB(lo, x - hx, y - hy);
}

__global__ __launch_bounds__(NT, 2)
void attn_mma_kernel(const float* __restrict__ Q,
                     const float* __restrict__ C,
                     const unsigned char* __restrict__ M,
                     float* __restrict__ out,
                     float* __restrict__ att)
{
    extern __shared__ uint32_t smw[];
    const unsigned short* CHIu = (const unsigned short*)(smw + SM_CHI);
    const unsigned short* CLOu = (const unsigned short*)(smw + SM_CLO);
    float* sums  = (float*)(smw + SM_SUMS);   // [32][4]
    float* rinvs = (float*)(smw + SM_RINV);   // [32]

    const int t    = threadIdx.x;
    const int lane = t & 31;
    const int w    = t >> 5;
    const int rh   = w >> 2;          // row half (16 rows)
    const int cq   = w & 3;           // seq quarter (64 cols)
    const int gi   = lane >> 2;       // 0..7
    const int ci   = lane & 3;        // 0..3
    const int row0 = rh*16 + gi;      // CTA-local rows row0, row0+8
    const int b    = blockIdx.y;
    const int q0   = blockIdx.x * BM;

    const float* Cg = C + (size_t)b * Lv * Dv;
    const unsigned char* Mg = M + (size_t)(b*Lv + q0) * Lv;
    float* attb = att + (size_t)(b*Lv + q0) * Lv;

    // ---- Q A-fragments in registers (hi/lo split, pre-scaled), once ----
    uint32_t qh[4][4], ql[4][4];
    {
        const float* Qr0 = Q + ((size_t)(b*Lv + q0 + row0)) * Dv;
        const float* Qr8 = Qr0 + 8*Dv;
        #pragma unroll
        for (int ks = 0; ks < 4; ++ks) {
            const int kc = ks*16 + 2*ci;
            const float2 v0 = *(const float2*)(Qr0 + kc);
            const float2 v1 = *(const float2*)(Qr8 + kc);
            const float2 v2 = *(const float2*)(Qr0 + kc + 8);
            const float2 v3 = *(const float2*)(Qr8 + kc + 8);
            split_pack(v0.x*SCALE, v0.y*SCALE, qh[ks][0], ql[ks][0]);
            split_pack(v1.x*SCALE, v1.y*SCALE, qh[ks][1], ql[ks][1]);
            split_pack(v2.x*SCALE, v2.y*SCALE, qh[ks][2], ql[ks][2]);
            split_pack(v3.x*SCALE, v3.y*SCALE, qh[ks][3], ql[ks][3]);
        }
    }

    float oacc[8][4];
    #pragma unroll
    for (int dt = 0; dt < 8; ++dt)
        { oacc[dt][0]=0.f; oacc[dt][1]=0.f; oacc[dt][2]=0.f; oacc[dt][3]=0.f; }
    float psum0 = 0.f, psum1 = 0.f;

    #pragma unroll 1
    for (int kt = 0; kt < NTILE; ++kt) {
        __syncthreads();   // prev tile's GEMMs done with C-tile
        // ---- stage C tile: fp32 -> bf16 hi/lo, [n][d-pair] rows stride CW ----
        {
            const float4* src4 = (const float4*)(Cg + (size_t)kt*BK*Dv);
            #pragma unroll
            for (int h = 0; h < 4; ++h) {
                float4 rr[4];
                #pragma unroll
                for (int j = 0; j < 4; ++j) rr[j] = src4[t + NT*(h*4 + j)];
                #pragma unroll
                for (int j = 0; j < 4; ++j) {
                    const int f4 = t + NT*(h*4 + j);
                    const int n  = f4 >> 4;
                    const int i2 = f4 & 15;
                    uint32_t h0, l0, h1, l1;
                    split_pack(rr[j].x, rr[j].y, h0, l0);
                    split_pack(rr[j].z, rr[j].w, h1, l1);
                    *(uint2*)(smw + SM_CHI + n*CW + 2*i2) = make_uint2(h0, h1);
                    *(uint2*)(smw + SM_CLO + n*CW + 2*i2) = make_uint2(l0, l1);
                }
            }
        }
        __syncthreads();   // staged

        // ---- per 16-seq-col group: GEMM1 -> exp -> GEMM2 ----
        #pragma unroll 1
        for (int u = 0; u < 4; ++u) {
            // GEMM1: S-tiles nt0 = cols [16u,16u+8), nt1 = [16u+8,16u+16)
            float D0[4] = {0.f,0.f,0.f,0.f};
            float D1[4] = {0.f,0.f,0.f,0.f};
            {
                const int nb = (cq*64 + 16*u + gi)*CW + ci;
                #pragma unroll
                for (int ks = 0; ks < 4; ++ks) {
                    const int r0 = nb + ks*8;
                    const uint32_t h00 = smw[SM_CHI + r0];
                    const uint32_t h01 = smw[SM_CHI + r0 + 4];
                    const uint32_t l00 = smw[SM_CLO + r0];
                    const uint32_t l01 = smw[SM_CLO + r0 + 4];
                    MMA(D0, qh[ks], h00, h01);
                    MMA(D0, ql[ks], h00, h01);
                    MMA(D0, qh[ks], l00, l01);
                    const int r1 = r0 + 8*CW;
                    const uint32_t h10 = smw[SM_CHI + r1];
                    const uint32_t h11 = smw[SM_CHI + r1 + 4];
                    const uint32_t l10 = smw[SM_CLO + r1];
                    const uint32_t l11 = smw[SM_CLO + r1 + 4];
                    MMA(D1, qh[ks], h10, h11);
                    MMA(D1, ql[ks], h10, h11);
                    MMA(D1, qh[ks], l10, l11);
                }
            }

            // exp + mask + psum + att store + P split (registers only)
            uint32_t phi[4], plo[4];
            #pragma unroll
            for (int ntl = 0; ntl < 2; ++ntl) {
                const float* Dp = ntl ? D1 : D0;
                const int col = kt*BK + cq*64 + 16*u + 8*ntl + 2*ci;
                const unsigned short m0 =
                    *(const unsigned short*)(Mg + (size_t)row0*Lv + col);
                const unsigned short m1 =
                    *(const unsigned short*)(Mg + (size_t)(row0+8)*Lv + col);
                const float e0 = (m0 & 0xff) ? 0.f : __expf(Dp[0]);
                const float e1 = (m0 >> 8)   ? 0.f : __expf(Dp[1]);
                const float e2 = (m1 & 0xff) ? 0.f : __expf(Dp[2]);
                const float e3 = (m1 >> 8)   ? 0.f : __expf(Dp[3]);
                psum0 += e0 + e1;
                psum1 += e2 + e3;
                *(float2*)(attb + (size_t)row0*Lv + col)     = make_float2(e0, e1);
                *(float2*)(attb + (size_t)(row0+8)*Lv + col) = make_float2(e2, e3);
                split_pack(e0, e1, phi[2*ntl],   plo[2*ntl]);
                split_pack(e2, e3, phi[2*ntl+1], plo[2*ntl+1]);
            }

            // GEMM2: out[16 x 64d] += P(16 x k16) * C(k16 x 64d)
            {
                const int k0 = cq*64 + 16*u + 2*ci;     // seq row in C-tile
                const unsigned short* pH0 = CHIu + (size_t)k0*(2*CW);
                const unsigned short* pL0 = CLOu + (size_t)k0*(2*CW);
                #pragma unroll
                for (int dt = 0; dt < 8; ++dt) {
                    const int dc = 8*dt + gi;
                    const uint32_t bh0 = (uint32_t)pH0[dc]
                                       | ((uint32_t)pH0[dc + 2*CW] << 16);
                    const uint32_t bh1 = (uint32_t)pH0[dc + 16*CW]
                                       | ((uint32_t)pH0[dc + 18*CW] << 16);
                    const uint32_t bl0 = (uint32_t)pL0[dc]
                                       | ((uint32_t)pL0[dc + 2*CW] << 16);
                    const uint32_t bl1 = (uint32_t)pL0[dc + 16*CW]
                                       | ((uint32_t)pL0[dc + 18*CW] << 16);
                    MMA(oacc[dt], phi, bh0, bh1);
                    MMA(oacc[dt], plo, bh0, bh1);
                    MMA(oacc[dt], phi, bl0, bl1);
                }
            }
        }
    }

    // ---- row sums -> rinvs ----
    psum0 += __shfl_xor_sync(0xffffffffu, psum0, 1);
    psum0 += __shfl_xor_sync(0xffffffffu, psum0, 2);
    psum1 += __shfl_xor_sync(0xffffffffu, psum1, 1);
    psum1 += __shfl_xor_sync(0xffffffffu, psum1, 2);
    if (ci == 0) {
        sums[row0*4 + cq]     = psum0;
        sums[(row0+8)*4 + cq] = psum1;
    }
    __syncthreads();
    if (t < BM) {
        const float s = (sums[t*4+0] + sums[t*4+1]) + (sums[t*4+2] + sums[t*4+3]);
        rinvs[t] = 1.0f / s;
    }
    __syncthreads();

    // ---- out: cross-warp (cq) reduction via smem (reuse CHI region) ----
    float* Ored = (float*)smw;   // 4*32*64 = 8192 floats <= 9216-word CHI
    #pragma unroll
    for (int dt = 0; dt < 8; ++dt) {
        *(float2*)(Ored + (cq*32 + row0)*64 + 8*dt + 2*ci) =
            make_float2(oacc[dt][0], oacc[dt][1]);
        *(float2*)(Ored + (cq*32 + row0+8)*64 + 8*dt + 2*ci) =
            make_float2(oacc[dt][2], oacc[dt][3]);
    }
    __syncthreads();
    #pragma unroll
    for (int i = 0; i < 8; ++i) {
        const int idx = t + NT*i;           // 0..2047
        const int row = idx >> 6, col = idx & 63;
        const float v = (Ored[(0*32 + row)*64 + col] + Ored[(1*32 + row)*64 + col])
                      + (Ored[(2*32 + row)*64 + col] + Ored[(3*32 + row)*64 + col]);
        out[(size_t)(b*Lv + q0 + row)*Dv + col] = v * rinvs[row];
    }

    // ---- normalize att in place (CTA owns its 32 rows) ----
    #pragma unroll
    for (int i = 0; i < 64; ++i) {
        const int idx = t + NT*i;           // 0..16383 float4
        const int row = idx >> 9, c4 = idx & 511;
        float4* p = (float4*)(attb + (size_t)row*Lv) + c4;
        float4 v = *p;
        const float rv = rinvs[row];
        v.x *= rv; v.y *= rv; v.z *= rv; v.w *= rv;
        *p = v;
    }
}

extern "C" void kernel_launch(void* const* d_in, const int* in_sizes, int n_in,
                              void* d_out, int out_size) {
    const float* Q = (const float*)d_in[0];
    const float* C = (const float*)d_in[1];
    const unsigned char* M = (const unsigned char*)d_in[2];

    float* out = (float*)d_out;                   // [B, L, D]
    float* att = out + (size_t)Bv * Lv * Dv;      // [B, L, L]

    const size_t smem_bytes = (size_t)SMEM_WORDS * 4;   // 74,368 B
    cudaFuncSetAttribute(attn_mma_kernel,
                         cudaFuncAttributeMaxDynamicSharedMemorySize,
                         (int)smem_bytes);

    dim3 grid(Lv / BM, Bv);
    attn_mma_kernel<<<grid, NT, smem_bytes>>>(Q, C, M, out, att);
}

// round 17
// speedup vs baseline: 2.2352x; 1.0095x over previous
#include <cuda_runtime.h>
#include <cuda_bf16.h>
#include <math.h>
#include <stdint.h>

#define Bv 8
#define Lv 2048
#define Dv 64
#define BM 32            // query rows per CTA
#define BK 256           // k-tile (seq)
#define NTILE (Lv/BK)    // 8
#define NT 256           // 8 warps = 2 row-halves x 4 seq-quarters
#define SCALE 0.125f

#define CW 36            // C-tile row stride in u32 words (mod 32 == 4 -> conflict-free)
#define SM_CHI  0
#define SM_CLO  (256*CW)            // 9216
#define SM_SUMS (2*256*CW)          // 18432 (float words)
#define SM_RINV (SM_SUMS + 128)
#define SMEM_WORDS (SM_RINV + 32)   // 18592 words = 74368 B -> 2 CTAs/SM

// pack 2 fp32 -> bf16x2 (lower half = lo_, upper = hi_)
#define PACKB(d_, lo_, hi_) \
    asm("cvt.rn.bf16x2.f32 %0, %1, %2;" : "=r"(d_) : "f"(hi_), "f"(lo_))

// D += A(bf16x2 x4) * B(bf16x2 x2)   [m16n8k16 row.col]
#define MMA(d_, a_, b0_, b1_) \
    asm volatile("mma.sync.aligned.m16n8k16.row.col.f32.bf16.bf16.f32 " \
        "{%0,%1,%2,%3}, {%4,%5,%6,%7}, {%8,%9}, {%0,%1,%2,%3};" \
        : "+f"((d_)[0]), "+f"((d_)[1]), "+f"((d_)[2]), "+f"((d_)[3]) \
        : "r"((a_)[0]), "r"((a_)[1]), "r"((a_)[2]), "r"((a_)[3]), \
          "r"(b0_), "r"(b1_))

__device__ __forceinline__ void split_pack(float x, float y,
                                           uint32_t& hi, uint32_t& lo) {
    PACKB(hi, x, y);
    const float hx = __uint_as_float(hi << 16);
    const float hy = __uint_as_float(hi & 0xffff0000u);
    PACKB(lo, x - hx, y - hy);
}

__global__ __launch_bounds__(NT, 2)
void attn_mma_kernel(const float* __restrict__ Q,
                     const float* __restrict__ C,
                     const unsigned char* __restrict__ M,
                     float* __restrict__ out,
                     float* __restrict__ att)
{
    extern __shared__ uint32_t smw[];
    const unsigned short* CHIu = (const unsigned short*)(smw + SM_CHI);
    const unsigned short* CLOu = (const unsigned short*)(smw + SM_CLO);
    float* sums  = (float*)(smw + SM_SUMS);   // [32][4]
    float* rinvs = (float*)(smw + SM_RINV);   // [32]

    const int t    = threadIdx.x;
    const int lane = t & 31;
    const int w    = t >> 5;
    const int rh   = w >> 2;          // row half (16 rows)
    const int cq   = w & 3;           // seq quarter (64 cols)
    const int gi   = lane >> 2;       // 0..7
    const int ci   = lane & 3;        // 0..3
    const int row0 = rh*16 + gi;      // CTA-local rows row0, row0+8
    const int b    = blockIdx.y;
    const int q0   = blockIdx.x * BM;

    const float* Cg = C + (size_t)b * Lv * Dv;
    const unsigned char* Mg = M + (size_t)(b*Lv + q0) * Lv;
    float* attb = att + (size_t)(b*Lv + q0) * Lv;

    // ---- Q A-fragments in registers (hi/lo split, pre-scaled), once ----
    uint32_t qh[4][4], ql[4][4];
    {
        const float* Qr0 = Q + ((size_t)(b*Lv + q0 + row0)) * Dv;
        const float* Qr8 = Qr0 + 8*Dv;
        #pragma unroll
        for (int ks = 0; ks < 4; ++ks) {
            const int kc = ks*16 + 2*ci;
            const float2 v0 = *(const float2*)(Qr0 + kc);
            const float2 v1 = *(const float2*)(Qr8 + kc);
            const float2 v2 = *(const float2*)(Qr0 + kc + 8);
            const float2 v3 = *(const float2*)(Qr8 + kc + 8);
            split_pack(v0.x*SCALE, v0.y*SCALE, qh[ks][0], ql[ks][0]);
            split_pack(v1.x*SCALE, v1.y*SCALE, qh[ks][1], ql[ks][1]);
            split_pack(v2.x*SCALE, v2.y*SCALE, qh[ks][2], ql[ks][2]);
            split_pack(v3.x*SCALE, v3.y*SCALE, qh[ks][3], ql[ks][3]);
        }
    }

    float oacc[8][4];
    #pragma unroll
    for (int dt = 0; dt < 8; ++dt)
        { oacc[dt][0]=0.f; oacc[dt][1]=0.f; oacc[dt][2]=0.f; oacc[dt][3]=0.f; }
    float psum0 = 0.f, psum1 = 0.f;

    #pragma unroll 1
    for (int kt = 0; kt < NTILE; ++kt) {
        __syncthreads();   // prev tile's GEMMs done with C-tile
        // ---- stage C tile: fp32 -> bf16 hi/lo; LDGs batched 8-wide (MLP) ----
        {
            const float4* src4 = (const float4*)(Cg + (size_t)kt*BK*Dv);
            #pragma unroll
            for (int h = 0; h < 2; ++h) {
                float4 rr[8];
                #pragma unroll
                for (int j = 0; j < 8; ++j) rr[j] = src4[t + NT*(h*8 + j)];
                #pragma unroll
                for (int j = 0; j < 8; ++j) {
                    const int f4 = t + NT*(h*8 + j);
                    const int n  = f4 >> 4;
                    const int i2 = f4 & 15;
                    uint32_t h0, l0, h1, l1;
                    split_pack(rr[j].x, rr[j].y, h0, l0);
                    split_pack(rr[j].z, rr[j].w, h1, l1);
                    *(uint2*)(smw + SM_CHI + n*CW + 2*i2) = make_uint2(h0, h1);
                    *(uint2*)(smw + SM_CLO + n*CW + 2*i2) = make_uint2(l0, l1);
                }
            }
        }
        __syncthreads();   // staged

        // ---- per 16-seq-col group: GEMM1 -> exp -> GEMM2 ----
        #pragma unroll 1
        for (int u = 0; u < 4; ++u) {
            // GEMM1 with per-split-term accumulators (chain depth 4, ILP 6)
            float D0a[4] = {0.f,0.f,0.f,0.f};
            float D0b[4] = {0.f,0.f,0.f,0.f};
            float D0c[4] = {0.f,0.f,0.f,0.f};
            float D1a[4] = {0.f,0.f,0.f,0.f};
            float D1b[4] = {0.f,0.f,0.f,0.f};
            float D1c[4] = {0.f,0.f,0.f,0.f};
            {
                const int nb = (cq*64 + 16*u + gi)*CW + ci;
                #pragma unroll
                for (int ks = 0; ks < 4; ++ks) {
                    const int r0 = nb + ks*8;
                    const uint32_t h00 = smw[SM_CHI + r0];
                    const uint32_t h01 = smw[SM_CHI + r0 + 4];
                    const uint32_t l00 = smw[SM_CLO + r0];
                    const uint32_t l01 = smw[SM_CLO + r0 + 4];
                    MMA(D0a, qh[ks], h00, h01);
                    MMA(D0b, ql[ks], h00, h01);
                    MMA(D0c, qh[ks], l00, l01);
                    const int r1 = r0 + 8*CW;
                    const uint32_t h10 = smw[SM_CHI + r1];
                    const uint32_t h11 = smw[SM_CHI + r1 + 4];
                    const uint32_t l10 = smw[SM_CLO + r1];
                    const uint32_t l11 = smw[SM_CLO + r1 + 4];
                    MMA(D1a, qh[ks], h10, h11);
                    MMA(D1b, ql[ks], h10, h11);
                    MMA(D1c, qh[ks], l10, l11);
                }
            }
            float D0[4], D1[4];
            #pragma unroll
            for (int i = 0; i < 4; ++i) {
                D0[i] = (D0a[i] + D0b[i]) + D0c[i];
                D1[i] = (D1a[i] + D1b[i]) + D1c[i];
            }

            // exp + mask + psum + att store + P split (registers only)
            uint32_t phi[4], plo[4];
            #pragma unroll
            for (int ntl = 0; ntl < 2; ++ntl) {
                const float* Dp = ntl ? D1 : D0;
                const int col = kt*BK + cq*64 + 16*u + 8*ntl + 2*ci;
                const unsigned short m0 =
                    *(const unsigned short*)(Mg + (size_t)row0*Lv + col);
                const unsigned short m1 =
                    *(const unsigned short*)(Mg + (size_t)(row0+8)*Lv + col);
                const float e0 = (m0 & 0xff) ? 0.f : __expf(Dp[0]);
                const float e1 = (m0 >> 8)   ? 0.f : __expf(Dp[1]);
                const float e2 = (m1 & 0xff) ? 0.f : __expf(Dp[2]);
                const float e3 = (m1 >> 8)   ? 0.f : __expf(Dp[3]);
                psum0 += e0 + e1;
                psum1 += e2 + e3;
                *(float2*)(attb + (size_t)row0*Lv + col)     = make_float2(e0, e1);
                *(float2*)(attb + (size_t)(row0+8)*Lv + col) = make_float2(e2, e3);
                split_pack(e0, e1, phi[2*ntl],   plo[2*ntl]);
                split_pack(e2, e3, phi[2*ntl+1], plo[2*ntl+1]);
            }

            // GEMM2: out[16 x 64d] += P(16 x k16) * C(k16 x 64d)
            {
                const int k0 = cq*64 + 16*u + 2*ci;     // seq row in C-tile
                const unsigned short* pH0 = CHIu + (size_t)k0*(2*CW);
                const unsigned short* pL0 = CLOu + (size_t)k0*(2*CW);
                #pragma unroll
                for (int dt = 0; dt < 8; ++dt) {
                    const int dc = 8*dt + gi;
                    const uint32_t bh0 = (uint32_t)pH0[dc]
                                       | ((uint32_t)pH0[dc + 2*CW] << 16);
                    const uint32_t bh1 = (uint32_t)pH0[dc + 16*CW]
                                       | ((uint32_t)pH0[dc + 18*CW] << 16);
                    const uint32_t bl0 = (uint32_t)pL0[dc]
                                       | ((uint32_t)pL0[dc + 2*CW] << 16);
                    const uint32_t bl1 = (uint32_t)pL0[dc + 16*CW]
                                       | ((uint32_t)pL0[dc + 18*CW] << 16);
                    MMA(oacc[dt], phi, bh0, bh1);
                    MMA(oacc[dt], plo, bh0, bh1);
                    MMA(oacc[dt], phi, bl0, bl1);
                }
            }
        }
    }

    // ---- row sums -> rinvs ----
    psum0 += __shfl_xor_sync(0xffffffffu, psum0, 1);
    psum0 += __shfl_xor_sync(0xffffffffu, psum0, 2);
    psum1 += __shfl_xor_sync(0xffffffffu, psum1, 1);
    psum1 += __shfl_xor_sync(0xffffffffu, psum1, 2);
    if (ci == 0) {
        sums[row0*4 + cq]     = psum0;
        sums[(row0+8)*4 + cq] = psum1;
    }
    __syncthreads();
    if (t < BM) {
        const float s = (sums[t*4+0] + sums[t*4+1]) + (sums[t*4+2] + sums[t*4+3]);
        rinvs[t] = 1.0f / s;
    }
    __syncthreads();

    // ---- out: cross-warp (cq) reduction via smem (reuse CHI region) ----
    float* Ored = (float*)smw;   // 4*32*64 = 8192 floats <= 9216-word CHI
    #pragma unroll
    for (int dt = 0; dt < 8; ++dt) {
        *(float2*)(Ored + (cq*32 + row0)*64 + 8*dt + 2*ci) =
            make_float2(oacc[dt][0], oacc[dt][1]);
        *(float2*)(Ored + (cq*32 + row0+8)*64 + 8*dt + 2*ci) =
            make_float2(oacc[dt][2], oacc[dt][3]);
    }
    __syncthreads();
    #pragma unroll
    for (int i = 0; i < 8; ++i) {
        const int idx = t + NT*i;           // 0..2047
        const int row = idx >> 6, col = idx & 63;
        const float v = (Ored[(0*32 + row)*64 + col] + Ored[(1*32 + row)*64 + col])
                      + (Ored[(2*32 + row)*64 + col] + Ored[(3*32 + row)*64 + col]);
        out[(size_t)(b*Lv + q0 + row)*Dv + col] = v * rinvs[row];
    }

    // ---- normalize att in place (CTA owns its 32 rows) ----
    #pragma unroll
    for (int i = 0; i < 64; ++i) {
        const int idx = t + NT*i;           // 0..16383 float4
        const int row = idx >> 9, c4 = idx & 511;
        float4* p = (float4*)(attb + (size_t)row*Lv) + c4;
        float4 v = *p;
        const float rv = rinvs[row];
        v.x *= rv; v.y *= rv; v.z *= rv; v.w *= rv;
        *p = v;
    }
}

extern "C" void kernel_launch(void* const* d_in, const int* in_sizes, int n_in,
                              void* d_out, int out_size) {
    const float* Q = (const float*)d_in[0];
    const float* C = (const float*)d_in[1];
    const unsigned char* M = (const unsigned char*)d_in[2];

    float* out = (float*)d_out;                   // [B, L, D]
    float* att = out + (size_t)Bv * Lv * Dv;      // [B, L, L]

    const size_t smem_bytes = (size_t)SMEM_WORDS * 4;   // 74,368 B
    cudaFuncSetAttribute(attn_mma_kernel,
                         cudaFuncAttributeMaxDynamicSharedMemorySize,
                         (int)smem_bytes);

    dim3 grid(Lv / BM, Bv);
    attn_mma_kernel<<<grid, NT, smem_bytes>>>(Q, C, M, out, att);
}